// round 8
// baseline (speedup 1.0000x reference)
#include <cuda_runtime.h>
#include <cstdint>

#define D    768
#define DV   (D / 4)    // 192 float4 per row
#define E    8
#define RB   4          // rows per warp-batch
#define NJ   12         // k-iterations (16 float4 per iter per half-warp)
#define NS   6          // cp.async pipeline stages (5 in flight)
#define WRP  8          // warps per CTA

typedef unsigned long long ull;

// packed 2-wide fp32 FMA: d = a*b + d
__device__ __forceinline__ void ffma2(ull& d, ull a, ull b) {
    asm("fma.rn.f32x2 %0, %1, %2, %0;" : "+l"(d) : "l"(a), "l"(b));
}
__device__ __forceinline__ uint32_t s2u(const void* p) {
    uint32_t a;
    asm("{ .reg .u64 t; cvta.to.shared.u64 t, %1; cvt.u32.u64 %0, t; }"
        : "=r"(a) : "l"(p));
    return a;
}
__device__ __forceinline__ void cpa16(uint32_t s, const float4* g) {
    asm volatile("cp.async.cg.shared.global [%0], [%1], 16;" :: "r"(s), "l"(g));
}
#define CP_COMMIT() asm volatile("cp.async.commit_group;")
#define CP_WAIT4()  asm volatile("cp.async.wait_group 4;")
#define CP_WAIT0()  asm volatile("cp.async.wait_group 0;")

__global__ __launch_bounds__(256, 3)
void router_kernel(const float* __restrict__ h,
                   const float* __restrict__ gw,
                   const float* __restrict__ gb,
                   float* __restrict__ out, int B) {
    extern __shared__ float4 smem[];
    float4* ws   = smem;                 // 8*DV float4 = 24 KB (row-major w copy)
    float4* xbuf = smem + 8 * DV;        // WRP*NS*64 float4 = 48 KB (h staging)
    float*  b_sh = (float*)(xbuf + WRP * NS * 64);   // 8 floats

    const float4* gw4 = reinterpret_cast<const float4*>(gw);
    for (int i = threadIdx.x; i < 8 * DV; i += blockDim.x)
        ws[i] = gw4[i];
    if (threadIdx.x < E) b_sh[threadIdx.x] = gb[threadIdx.x];
    __syncthreads();

    const ulonglong2* wsu = reinterpret_cast<const ulonglong2*>(ws);

    const int lane   = threadIdx.x & 31;
    const int half   = lane >> 4;        // 0: rows {0,1}, 1: rows {2,3}
    const int kl     = lane & 15;        // k-slot within half-warp
    const int warp   = threadIdx.x >> 5;
    const int gwarp  = blockIdx.x * WRP + warp;
    const int nwarps = gridDim.x * WRP;
    const int nbatch = B / RB;

    // thread-private staging slots (per warp: NS stages x 64 float4)
    float4* xw = xbuf + warp * (NS * 64);
    const uint32_t xs0 = s2u(xw) + (uint32_t)((2 * half + 0) * 16 + kl) * 16u;
    const uint32_t xs1 = s2u(xw) + (uint32_t)((2 * half + 1) * 16 + kl) * 16u;
    const ulonglong2* xr0 = reinterpret_cast<const ulonglong2*>(xw + (2 * half + 0) * 16 + kl);
    const ulonglong2* xr1 = reinterpret_cast<const ulonglong2*>(xw + (2 * half + 1) * 16 + kl);

    float* out_idx = out;                       // [B,2] indices (as float)
    float* out_wt  = out + (size_t)2 * B;       // [B,2] weights
    float* out_lg  = out + (size_t)4 * B;       // [B,8] logits

    const float4* h4 = reinterpret_cast<const float4*>(h);

    for (int batch = gwarp; batch < nbatch; batch += nwarps) {
        const int row0 = batch * RB;
        const float4* g0 = h4 + (size_t)(row0 + 2 * half) * DV + kl;  // row a
        const float4* g1 = g0 + DV;                                    // row a+1

        // prologue: stages 0..NS-2 (5 KB/warp in flight immediately)
        #pragma unroll
        for (int s = 0; s < NS - 1; s++) {
            cpa16(xs0 + (uint32_t)(s * 1024), g0 + s * 16);
            cpa16(xs1 + (uint32_t)(s * 1024), g1 + s * 16);
            CP_COMMIT();
        }

        // acc2[r][e]: low half = even k-pair partial, high half = odd
        ull acc2[2][E];
        #pragma unroll
        for (int r = 0; r < 2; r++)
            #pragma unroll
            for (int e = 0; e < E; e++) acc2[r][e] = 0ull;

        #pragma unroll
        for (int j = 0; j < NJ; j++) {          // full unroll: j%NS compile-time
            CP_WAIT4();                         // stage j complete (4 newer pending)

            const int st = j % NS;
            const ulonglong2 xu0 = xr0[st * 64];   // LDS.128, thread-private
            const ulonglong2 xu1 = xr1[st * 64];

            if (j < NJ - (NS - 1)) {            // issue stage j+NS-1
                const int jn = j + NS - 1;
                cpa16(xs0 + (uint32_t)((jn % NS) * 1024), g0 + jn * 16);
                cpa16(xs1 + (uint32_t)((jn % NS) * 1024), g1 + jn * 16);
            }
            CP_COMMIT();                        // empty commit keeps counts aligned

            const int k4 = j * 16 + kl;
            #pragma unroll
            for (int e = 0; e < E; e++) {
                // both half-warps read same address -> LDS broadcast (2 wf)
                const ulonglong2 we = wsu[e * DV + k4];
                ffma2(acc2[0][e], we.x, xu0.x);
                ffma2(acc2[0][e], we.y, xu0.y);
                ffma2(acc2[1][e], we.x, xu1.x);
                ffma2(acc2[1][e], we.y, xu1.y);
            }
        }
        CP_WAIT0();   // drain trailing empty groups before next batch reuses slots

        // unpack + horizontal add: v[r*8 + e] for local rows r in {0,1}
        float v[16];
        #pragma unroll
        for (int r = 0; r < 2; r++)
            #pragma unroll
            for (int e = 0; e < E; e++) {
                uint32_t lo, hi;
                asm("mov.b64 {%0, %1}, %2;" : "=r"(lo), "=r"(hi) : "l"(acc2[r][e]));
                v[r * E + e] = __uint_as_float(lo) + __uint_as_float(hi);
            }

        // Butterfly transpose-reduce within each 16-lane half (offsets 8..1)
        #pragma unroll
        for (int off = 8; off >= 1; off >>= 1) {
            const bool up = (kl & off) != 0;
            #pragma unroll
            for (int i = 0; i < off; i++) {
                float send = up ? v[i] : v[i + off];
                float recv = __shfl_xor_sync(0xffffffffu, send, off);
                v[i] = (up ? v[i + off] : v[i]) + recv;
            }
        }

        // lane l -> row = row0 + (l>>3), expert e = l&7
        const int e   = lane & 7;
        const int row = row0 + (lane >> 3);
        const float logit = v[0] + b_sh[e];

        out_lg[(size_t)row * E + e] = logit;     // 32 consecutive floats/warp

        float lv[8];
        #pragma unroll
        for (int k = 0; k < 8; k++)
            lv[k] = __shfl_sync(0xffffffffu, logit, (lane & 24) | k);

        if (e == 0) {
            // top-1: strict >, lowest index wins ties (matches lax.top_k)
            int i1 = 0; float v1 = lv[0];
            #pragma unroll
            for (int k = 1; k < 8; k++)
                if (lv[k] > v1) { v1 = lv[k]; i1 = k; }
            int i2 = (i1 == 0) ? 1 : 0; float v2 = lv[i2];
            #pragma unroll
            for (int k = 0; k < 8; k++)
                if (k != i1 && lv[k] > v2) { v2 = lv[k]; i2 = k; }

            const float t  = __expf(v2 - v1);     // <= 1
            const float w1 = 1.0f / (1.0f + t);
            const float w2 = t * w1;

            out_idx[(size_t)row * 2]     = (float)i1;
            out_idx[(size_t)row * 2 + 1] = (float)i2;
            out_wt [(size_t)row * 2]     = w1;
            out_wt [(size_t)row * 2 + 1] = w2;
        }
    }
}

extern "C" void kernel_launch(void* const* d_in, const int* in_sizes, int n_in,
                              void* d_out, int out_size) {
    const float* h  = (const float*)d_in[0];   // [B, 768]
    const float* gw = (const float*)d_in[1];   // [8, 768]
    const float* gb = (const float*)d_in[2];   // [8]
    float* out = (float*)d_out;

    const int B = in_sizes[0] / D;             // 32768

    // smem: 24KB weights + 48KB x staging + bias
    const int smem_bytes = (8 * DV + WRP * NS * 64) * 16 + 64;
    cudaFuncSetAttribute(router_kernel,
                         cudaFuncAttributeMaxDynamicSharedMemorySize, smem_bytes);

    // 444 = 3 x 148: 3 CTAs/SM (73.8 KB smem each), deep per-warp pipelines.
    const int threads = 256;
    const int blocks  = 444;
    router_kernel<<<blocks, threads, smem_bytes>>>(h, gw, gb, out, B);
}

// round 9
// speedup vs baseline: 1.0106x; 1.0106x over previous
#include <cuda_runtime.h>
#include <cstdint>

#define D    768
#define DV   (D / 4)    // 192 float4 per row
#define E    8
#define RB   4          // rows per warp-batch
#define NJ   12         // k-iterations (16 float4 columns per iter per half-warp)
#define NS   3          // cp.async pipeline stages
#define WRP  8          // warps per CTA

typedef unsigned long long ull;

// packed 2-wide fp32 FMA: d = a*b + d
__device__ __forceinline__ void ffma2(ull& d, ull a, ull b) {
    asm("fma.rn.f32x2 %0, %1, %2, %0;" : "+l"(d) : "l"(a), "l"(b));
}
__device__ __forceinline__ uint32_t s2u(const void* p) {
    uint32_t a;
    asm("{ .reg .u64 t; cvta.to.shared.u64 t, %1; cvt.u32.u64 %0, t; }"
        : "=r"(a) : "l"(p));
    return a;
}
// L2 eviction policy: keep h resident across graph replays (L2 = 126MB > 96MB)
__device__ __forceinline__ ull mkpolicy_evict_last() {
    ull p;
    asm("createpolicy.fractional.L2::evict_last.b64 %0, 1.0;" : "=l"(p));
    return p;
}
__device__ __forceinline__ void cpa16(uint32_t s, const float4* g, ull pol) {
    asm volatile("cp.async.cg.shared.global.L2::cache_hint [%0], [%1], 16, %2;"
                 :: "r"(s), "l"(g), "l"(pol));
}
#define CP_COMMIT() asm volatile("cp.async.commit_group;")
#define CP_WAIT1()  asm volatile("cp.async.wait_group 1;")

__global__ __launch_bounds__(256, 4)
void router_kernel(const float* __restrict__ h,
                   const float* __restrict__ gw,
                   const float* __restrict__ gb,
                   float* __restrict__ out, int B) {
    extern __shared__ float4 smem[];
    float4* ws   = smem;                 // 8*DV float4 = 24 KB (row-major w copy)
    float4* xbuf = smem + 8 * DV;        // WRP*NS*64 float4 = 24 KB (h staging)
    float*  b_sh = (float*)(xbuf + WRP * NS * 64);   // 8 floats

    const float4* gw4 = reinterpret_cast<const float4*>(gw);
    for (int i = threadIdx.x; i < 8 * DV; i += blockDim.x)
        ws[i] = gw4[i];
    if (threadIdx.x < E) b_sh[threadIdx.x] = gb[threadIdx.x];
    __syncthreads();

    const ulonglong2* wsu = reinterpret_cast<const ulonglong2*>(ws);
    const ull pol = mkpolicy_evict_last();

    const int lane   = threadIdx.x & 31;
    const int half   = lane >> 4;        // 0: rows {0,1}, 1: rows {2,3}
    const int kl     = lane & 15;        // k-slot within half-warp
    const int warp   = threadIdx.x >> 5;
    const int gwarp  = blockIdx.x * WRP + warp;
    const int nwarps = gridDim.x * WRP;
    const int nbatch = B / RB;

    // thread-private staging slots: rows (2*half+0) and (2*half+1), slot kl
    float4* xw = xbuf + warp * (NS * 64);
    const uint32_t xs0 = s2u(xw) + (uint32_t)((2 * half + 0) * 16 + kl) * 16u;
    const uint32_t xs1 = s2u(xw) + (uint32_t)((2 * half + 1) * 16 + kl) * 16u;
    const ulonglong2* xr0 = reinterpret_cast<const ulonglong2*>(xw + (2 * half + 0) * 16 + kl);
    const ulonglong2* xr1 = reinterpret_cast<const ulonglong2*>(xw + (2 * half + 1) * 16 + kl);

    float* out_idx = out;                       // [B,2] indices (as float)
    float* out_wt  = out + (size_t)2 * B;       // [B,2] weights
    float* out_lg  = out + (size_t)4 * B;       // [B,8] logits

    const float4* h4 = reinterpret_cast<const float4*>(h);

    for (int batch = gwarp; batch < nbatch; batch += nwarps) {
        const int row0 = batch * RB;
        const float4* g0 = h4 + (size_t)(row0 + 2 * half) * DV + kl;  // row a
        const float4* g1 = g0 + DV;                                    // row a+1

        // prologue: stages for j = 0 .. NS-2
        #pragma unroll
        for (int s = 0; s < NS - 1; s++) {
            cpa16(xs0 + (uint32_t)(s * 1024), g0 + s * 16, pol);
            cpa16(xs1 + (uint32_t)(s * 1024), g1 + s * 16, pol);
            CP_COMMIT();
        }

        // acc2[r][e]: low half = even k-pair partial, high half = odd
        ull acc2[2][E];
        #pragma unroll
        for (int r = 0; r < 2; r++)
            #pragma unroll
            for (int e = 0; e < E; e++) acc2[r][e] = 0ull;

        #pragma unroll 1
        for (int j = 0; j < NJ; j++) {
            CP_WAIT1();                        // stage j complete

            const int st = j % NS;
            const ulonglong2 xu0 = xr0[st * 64];   // LDS.128, thread-private
            const ulonglong2 xu1 = xr1[st * 64];

            if (j < NJ - (NS - 1)) {           // issue stage j+NS-1
                const int jn = j + NS - 1;
                cpa16(xs0 + (uint32_t)((jn % NS) * 1024), g0 + jn * 16, pol);
                cpa16(xs1 + (uint32_t)((jn % NS) * 1024), g1 + jn * 16, pol);
            }
            CP_COMMIT();                       // empty commit keeps counts aligned

            const int k4 = j * 16 + kl;
            #pragma unroll
            for (int e = 0; e < E; e++) {
                // both half-warps read same address -> LDS broadcast
                const ulonglong2 we = wsu[e * DV + k4];
                ffma2(acc2[0][e], we.x, xu0.x);
                ffma2(acc2[0][e], we.y, xu0.y);
                ffma2(acc2[1][e], we.x, xu1.x);
                ffma2(acc2[1][e], we.y, xu1.y);
            }
        }

        // unpack + horizontal add: v[r*8 + e] for local rows r in {0,1}
        float v[16];
        #pragma unroll
        for (int r = 0; r < 2; r++)
            #pragma unroll
            for (int e = 0; e < E; e++) {
                uint32_t lo, hi;
                asm("mov.b64 {%0, %1}, %2;" : "=r"(lo), "=r"(hi) : "l"(acc2[r][e]));
                v[r * E + e] = __uint_as_float(lo) + __uint_as_float(hi);
            }

        // Butterfly transpose-reduce within each 16-lane half (offsets 8..1):
        // afterwards lane l holds the full sum of local index (l & 15).
        #pragma unroll
        for (int off = 8; off >= 1; off >>= 1) {
            const bool up = (kl & off) != 0;
            #pragma unroll
            for (int i = 0; i < off; i++) {
                float send = up ? v[i] : v[i + off];
                float recv = __shfl_xor_sync(0xffffffffu, send, off);
                v[i] = (up ? v[i + off] : v[i]) + recv;
            }
        }

        // lane l -> row = row0 + (l>>3), expert e = l&7
        const int e   = lane & 7;
        const int row = row0 + (lane >> 3);
        const float logit = v[0] + b_sh[e];

        out_lg[(size_t)row * E + e] = logit;     // 32 consecutive floats/warp

        float lv[8];
        #pragma unroll
        for (int k = 0; k < 8; k++)
            lv[k] = __shfl_sync(0xffffffffu, logit, (lane & 24) | k);

        if (e == 0) {
            // top-1: strict >, lowest index wins ties (matches lax.top_k)
            int i1 = 0; float v1 = lv[0];
            #pragma unroll
            for (int k = 1; k < 8; k++)
                if (lv[k] > v1) { v1 = lv[k]; i1 = k; }
            int i2 = (i1 == 0) ? 1 : 0; float v2 = lv[i2];
            #pragma unroll
            for (int k = 0; k < 8; k++)
                if (k != i1 && lv[k] > v2) { v2 = lv[k]; i2 = k; }

            const float t  = __expf(v2 - v1);     // <= 1
            const float w1 = 1.0f / (1.0f + t);
            const float w2 = t * w1;

            out_idx[(size_t)row * 2]     = (float)i1;
            out_idx[(size_t)row * 2 + 1] = (float)i2;
            out_wt [(size_t)row * 2]     = w1;
            out_wt [(size_t)row * 2 + 1] = w2;
        }
    }
}

extern "C" void kernel_launch(void* const* d_in, const int* in_sizes, int n_in,
                              void* d_out, int out_size) {
    const float* h  = (const float*)d_in[0];   // [B, 768]
    const float* gw = (const float*)d_in[1];   // [8, 768]
    const float* gb = (const float*)d_in[2];   // [8]
    float* out = (float*)d_out;

    const int B = in_sizes[0] / D;             // 32768

    // smem: 24KB weights + 24KB x staging + bias
    const int smem_bytes = (8 * DV + WRP * NS * 64) * 16 + 64;
    cudaFuncSetAttribute(router_kernel,
                         cudaFuncAttributeMaxDynamicSharedMemorySize, smem_bytes);

    // 592 = 4 x 148: exactly 4 CTAs per SM in a single wave (occ 4).
    const int threads = 256;
    const int blocks  = 592;
    router_kernel<<<blocks, threads, smem_bytes>>>(h, gw, gb, out, B);
}

// round 10
// speedup vs baseline: 1.1905x; 1.1780x over previous
#include <cuda_runtime.h>
#include <cstdint>

#define D        768
#define DV       (D / 4)     // 192 float4 per row
#define E        8
#define TR       32          // rows per tile (96 KB)
#define WR       4           // rows per warp
#define NJ       6           // k-iterations (32 float4 per iter)
#define THREADS  256
#define TILE_BYTES (TR * D * 4)   // 98304

typedef unsigned long long ull;

// packed 2-wide fp32 FMA: d = a*b + d
__device__ __forceinline__ void ffma2(ull& d, ull a, ull b) {
    asm("fma.rn.f32x2 %0, %1, %2, %0;" : "+l"(d) : "l"(a), "l"(b));
}
__device__ __forceinline__ uint32_t s2u(const void* p) {
    uint32_t a;
    asm("{ .reg .u64 t; cvta.to.shared.u64 t, %1; cvt.u32.u64 %0, t; }"
        : "=r"(a) : "l"(p));
    return a;
}
__device__ __forceinline__ void mbar_init(uint32_t m, uint32_t cnt) {
    asm volatile("mbarrier.init.shared.b64 [%0], %1;" :: "r"(m), "r"(cnt) : "memory");
}
__device__ __forceinline__ void mbar_expect_tx(uint32_t m, uint32_t bytes) {
    asm volatile("mbarrier.arrive.expect_tx.shared.b64 _, [%0], %1;"
                 :: "r"(m), "r"(bytes) : "memory");
}
__device__ __forceinline__ void mbar_wait(uint32_t m, uint32_t phase) {
    asm volatile(
        "{\n\t"
        ".reg .pred P1;\n\t"
        "LAB_WAIT_%=:\n\t"
        "mbarrier.try_wait.parity.acquire.cta.shared::cta.b64 P1, [%0], %1, 0x989680;\n\t"
        "@P1 bra LAB_DONE_%=;\n\t"
        "bra LAB_WAIT_%=;\n\t"
        "LAB_DONE_%=:\n\t"
        "}"
        :: "r"(m), "r"(phase) : "memory");
}
// 1D bulk copy global -> shared (TMA engine, no per-warp LSU traffic)
__device__ __forceinline__ void bulk_g2s(uint32_t dst, const void* src,
                                         uint32_t bytes, uint32_t m) {
    asm volatile(
        "cp.async.bulk.shared::cta.global.mbarrier::complete_tx::bytes [%0], [%1], %2, [%3];"
        :: "r"(dst), "l"(src), "r"(bytes), "r"(m) : "memory");
}

__global__ __launch_bounds__(THREADS, 1)
void router_kernel(const float* __restrict__ h,
                   const float* __restrict__ gw,
                   const float* __restrict__ gb,
                   float* __restrict__ out, int B) {
    extern __shared__ float4 smem[];
    float4* ws  = smem;                         // 1536 float4 = 24 KB (row-major w)
    float4* xb0 = smem + 8 * DV;                // 6144 float4 = 96 KB (tile buf 0)
    float4* xb1 = xb0 + TR * DV;                // 96 KB (tile buf 1)
    float*  b_sh = (float*)(xb1 + TR * DV);     // 8 floats
    uint64_t* mbar = (uint64_t*)(b_sh + 8);     // 2 mbarriers (8B aligned)

    const float4* gw4 = reinterpret_cast<const float4*>(gw);
    for (int i = threadIdx.x; i < 8 * DV; i += THREADS)
        ws[i] = gw4[i];
    if (threadIdx.x < E) b_sh[threadIdx.x] = gb[threadIdx.x];

    const uint32_t mb0 = s2u(mbar);
    const uint32_t mb1 = mb0 + 8;
    const uint32_t xs0 = s2u(xb0);
    const uint32_t xs1 = s2u(xb1);

    if (threadIdx.x == 0) {
        mbar_init(mb0, 1);
        mbar_init(mb1, 1);
        asm volatile("fence.proxy.async.shared::cta;" ::: "memory");
    }
    __syncthreads();

    const ulonglong2* wsu = reinterpret_cast<const ulonglong2*>(ws);

    const int lane = threadIdx.x & 31;
    const int warp = threadIdx.x >> 5;
    const int NT   = B / TR;                    // 1024 tiles

    float* out_idx = out;                       // [B,2] indices (as float)
    float* out_wt  = out + (size_t)2 * B;       // [B,2] weights
    float* out_lg  = out + (size_t)4 * B;       // [B,8] logits

    // prologue: issue first tile into buf 0
    if (blockIdx.x < NT && threadIdx.x == 0) {
        mbar_expect_tx(mb0, TILE_BYTES);
        bulk_g2s(xs0, h + (size_t)blockIdx.x * TR * D, TILE_BYTES, mb0);
    }

    int t = 0;
    for (int tile = blockIdx.x; tile < NT; tile += gridDim.x, t++) {
        const int buf = t & 1;

        // issue next tile into the other buffer (free since end of iter t-1)
        const int ntile = tile + gridDim.x;
        if (ntile < NT && threadIdx.x == 0) {
            const uint32_t mbn = (buf ^ 1) ? mb1 : mb0;
            const uint32_t xsn = (buf ^ 1) ? xs1 : xs0;
            mbar_expect_tx(mbn, TILE_BYTES);
            bulk_g2s(xsn, h + (size_t)ntile * TR * D, TILE_BYTES, mbn);
        }

        // wait for current tile (phase flips every 2nd use of each barrier)
        mbar_wait(buf ? mb1 : mb0, (t >> 1) & 1);

        const float4* xt = (buf ? xb1 : xb0) + warp * WR * DV;  // 4 rows/warp
        const int row0 = tile * TR + warp * WR;

        // acc2[r][e]: packed k-pairs (low = even pair, high = odd pair)
        ull acc2[WR][E];
        #pragma unroll
        for (int r = 0; r < WR; r++)
            #pragma unroll
            for (int e = 0; e < E; e++) acc2[r][e] = 0ull;

        #pragma unroll
        for (int j = 0; j < NJ; j++) {
            const int k4 = j * 32 + lane;
            ulonglong2 xu[WR];
            #pragma unroll
            for (int r = 0; r < WR; r++)
                xu[r] = *reinterpret_cast<const ulonglong2*>(&xt[r * DV + k4]);
            #pragma unroll
            for (int e = 0; e < E; e++) {
                const ulonglong2 we = wsu[e * DV + k4];
                #pragma unroll
                for (int r = 0; r < WR; r++) {
                    ffma2(acc2[r][e], we.x, xu[r].x);
                    ffma2(acc2[r][e], we.y, xu[r].y);
                }
            }
        }

        // unpack + horizontal add: v[r*8 + e]
        float v[WR * E];
        #pragma unroll
        for (int r = 0; r < WR; r++)
            #pragma unroll
            for (int e = 0; e < E; e++) {
                uint32_t lo, hi;
                asm("mov.b64 {%0, %1}, %2;" : "=r"(lo), "=r"(hi) : "l"(acc2[r][e]));
                v[r * E + e] = __uint_as_float(lo) + __uint_as_float(hi);
            }

        // Butterfly transpose-reduction over 32 lanes / 32 values:
        // lane l ends with the full k-sum of value index l (row l>>3, expert l&7).
        #pragma unroll
        for (int off = 16; off >= 1; off >>= 1) {
            const bool up = (lane & off) != 0;
            #pragma unroll
            for (int i = 0; i < off; i++) {
                float send = up ? v[i] : v[i + off];
                float recv = __shfl_xor_sync(0xffffffffu, send, off);
                v[i] = (up ? v[i + off] : v[i]) + recv;
            }
        }

        const int e   = lane & 7;
        const int row = row0 + (lane >> 3);
        const float logit = v[0] + b_sh[e];

        out_lg[(size_t)row * E + e] = logit;     // 32 consecutive floats/warp

        float lv[8];
        #pragma unroll
        for (int k = 0; k < 8; k++)
            lv[k] = __shfl_sync(0xffffffffu, logit, (lane & 24) | k);

        if (e == 0) {
            // top-1: strict >, lowest index wins ties (matches lax.top_k)
            int i1 = 0; float v1 = lv[0];
            #pragma unroll
            for (int k = 1; k < 8; k++)
                if (lv[k] > v1) { v1 = lv[k]; i1 = k; }
            int i2 = (i1 == 0) ? 1 : 0; float v2 = lv[i2];
            #pragma unroll
            for (int k = 0; k < 8; k++)
                if (k != i1 && lv[k] > v2) { v2 = lv[k]; i2 = k; }

            const float tt = __expf(v2 - v1);     // <= 1
            const float w1 = 1.0f / (1.0f + tt);
            const float w2 = tt * w1;

            out_idx[(size_t)row * 2]     = (float)i1;
            out_idx[(size_t)row * 2 + 1] = (float)i2;
            out_wt [(size_t)row * 2]     = w1;
            out_wt [(size_t)row * 2 + 1] = w2;
        }

        // all threads done with this buffer before it is refilled at t+2
        __syncthreads();
    }
}

extern "C" void kernel_launch(void* const* d_in, const int* in_sizes, int n_in,
                              void* d_out, int out_size) {
    const float* h  = (const float*)d_in[0];   // [B, 768]
    const float* gw = (const float*)d_in[1];   // [8, 768]
    const float* gb = (const float*)d_in[2];   // [8]
    float* out = (float*)d_out;

    const int B = in_sizes[0] / D;             // 32768

    // smem: 24KB w + 2 x 96KB tile buffers + bias + mbarriers
    const int smem_bytes = (8 * DV + 2 * TR * DV) * 16 + 64;
    cudaFuncSetAttribute(router_kernel,
                         cudaFuncAttributeMaxDynamicSharedMemorySize, smem_bytes);

    // persistent: 1 CTA per SM, grid-stride over 1024 tiles
    const int blocks = 148;
    router_kernel<<<blocks, THREADS, smem_bytes>>>(h, gw, gb, out, B);
}

// round 11
// speedup vs baseline: 1.3069x; 1.0977x over previous
#include <cuda_runtime.h>
#include <cstdint>

#define D        768
#define DV       (D / 4)     // 192 float4 per row
#define E        8
#define RB       4           // rows per warp-batch
#define NJ       6           // k-iterations (32 float4 per iter)
#define WRP      8           // warps per CTA
#define THREADS  256
#define SLOT     (RB * DV)           // 768 float4 = 12 KB per buffer
#define SLOT_BYTES (RB * D * 4)      // 12288

typedef unsigned long long ull;

// packed 2-wide fp32 FMA: d = a*b + d
__device__ __forceinline__ void ffma2(ull& d, ull a, ull b) {
    asm("fma.rn.f32x2 %0, %1, %2, %0;" : "+l"(d) : "l"(a), "l"(b));
}
__device__ __forceinline__ uint32_t s2u(const void* p) {
    uint32_t a;
    asm("{ .reg .u64 t; cvta.to.shared.u64 t, %1; cvt.u32.u64 %0, t; }"
        : "=r"(a) : "l"(p));
    return a;
}
__device__ __forceinline__ void mbar_init(uint32_t m, uint32_t cnt) {
    asm volatile("mbarrier.init.shared.b64 [%0], %1;" :: "r"(m), "r"(cnt) : "memory");
}
__device__ __forceinline__ void mbar_expect_tx(uint32_t m, uint32_t bytes) {
    asm volatile("mbarrier.arrive.expect_tx.shared.b64 _, [%0], %1;"
                 :: "r"(m), "r"(bytes) : "memory");
}
__device__ __forceinline__ void mbar_wait(uint32_t m, uint32_t phase) {
    asm volatile(
        "{\n\t"
        ".reg .pred P1;\n\t"
        "LAB_WAIT_%=:\n\t"
        "mbarrier.try_wait.parity.acquire.cta.shared::cta.b64 P1, [%0], %1, 0x989680;\n\t"
        "@P1 bra LAB_DONE_%=;\n\t"
        "bra LAB_WAIT_%=;\n\t"
        "LAB_DONE_%=:\n\t"
        "}"
        :: "r"(m), "r"(phase) : "memory");
}
// 1D bulk copy global -> shared (TMA engine, no per-warp LSU traffic)
__device__ __forceinline__ void bulk_g2s(uint32_t dst, const void* src,
                                         uint32_t bytes, uint32_t m) {
    asm volatile(
        "cp.async.bulk.shared::cta.global.mbarrier::complete_tx::bytes [%0], [%1], %2, [%3];"
        :: "r"(dst), "l"(src), "r"(bytes), "r"(m) : "memory");
}

__global__ __launch_bounds__(THREADS, 1)
void router_kernel(const float* __restrict__ h,
                   const float* __restrict__ gw,
                   const float* __restrict__ gb,
                   float* __restrict__ out, int B) {
    extern __shared__ float4 smem[];
    float4* ws   = smem;                        // 1536 float4 = 24 KB (row-major w)
    float4* xbuf = smem + 8 * DV;               // WRP*2*SLOT = 192 KB staging
    float*  b_sh = (float*)(xbuf + WRP * 2 * SLOT);   // 8 floats
    uint64_t* mbars = (uint64_t*)(b_sh + 8);    // 16 mbarriers (warp, buf)

    const float4* gw4 = reinterpret_cast<const float4*>(gw);
    for (int i = threadIdx.x; i < 8 * DV; i += THREADS)
        ws[i] = gw4[i];
    if (threadIdx.x < E) b_sh[threadIdx.x] = gb[threadIdx.x];

    if (threadIdx.x == 0) {
        for (int i = 0; i < WRP * 2; i++)
            mbar_init(s2u(mbars) + 8u * i, 1);
        asm volatile("fence.proxy.async.shared::cta;" ::: "memory");
    }
    __syncthreads();   // the ONLY CTA-wide sync in the kernel

    const ulonglong2* wsu = reinterpret_cast<const ulonglong2*>(ws);

    const int lane   = threadIdx.x & 31;
    const int warp   = threadIdx.x >> 5;
    const int gwarp  = blockIdx.x * WRP + warp;
    const int nwarps = gridDim.x * WRP;
    const int nbatch = B / RB;                  // 8192

    // warp-private double buffer + mbarriers
    float4* xw = xbuf + warp * (2 * SLOT);
    const uint32_t xs0 = s2u(xw);
    const uint32_t xs1 = xs0 + SLOT_BYTES;
    const uint32_t mb0 = s2u(mbars) + (uint32_t)warp * 16u;
    const uint32_t mb1 = mb0 + 8u;

    float* out_idx = out;                       // [B,2] indices (as float)
    float* out_wt  = out + (size_t)2 * B;       // [B,2] weights
    float* out_lg  = out + (size_t)4 * B;       // [B,8] logits

    // prologue: issue first two batches (warp-private, lane 0 only)
    if (lane == 0) {
        if (gwarp < nbatch) {
            mbar_expect_tx(mb0, SLOT_BYTES);
            bulk_g2s(xs0, h + (size_t)gwarp * RB * D, SLOT_BYTES, mb0);
        }
        if (gwarp + nwarps < nbatch) {
            mbar_expect_tx(mb1, SLOT_BYTES);
            bulk_g2s(xs1, h + (size_t)(gwarp + nwarps) * RB * D, SLOT_BYTES, mb1);
        }
    }

    int i = 0;
    for (int batch = gwarp; batch < nbatch; batch += nwarps, i++) {
        const int buf = i & 1;
        mbar_wait(buf ? mb1 : mb0, (i >> 1) & 1);   // wait own 12 KB only

        const float4* xt = xw + buf * SLOT;
        const int row0 = batch * RB;

        // acc2[r][e]: packed k-pairs (low = even pair, high = odd pair)
        ull acc2[RB][E];
        #pragma unroll
        for (int r = 0; r < RB; r++)
            #pragma unroll
            for (int e = 0; e < E; e++) acc2[r][e] = 0ull;

        #pragma unroll
        for (int j = 0; j < NJ; j++) {
            const int k4 = j * 32 + lane;
            ulonglong2 xu[RB];
            #pragma unroll
            for (int r = 0; r < RB; r++)
                xu[r] = *reinterpret_cast<const ulonglong2*>(&xt[r * DV + k4]);
            #pragma unroll
            for (int e = 0; e < E; e++) {
                const ulonglong2 we = wsu[e * DV + k4];
                #pragma unroll
                for (int r = 0; r < RB; r++) {
                    ffma2(acc2[r][e], we.x, xu[r].x);
                    ffma2(acc2[r][e], we.y, xu[r].y);
                }
            }
        }

        // refill this slot with batch i+2 (warp-private; reads above are done)
        __syncwarp();
        if (lane == 0) {
            const int nb = batch + 2 * nwarps;
            if (nb < nbatch) {
                const uint32_t mbn = buf ? mb1 : mb0;
                mbar_expect_tx(mbn, SLOT_BYTES);
                bulk_g2s(buf ? xs1 : xs0, h + (size_t)nb * RB * D, SLOT_BYTES, mbn);
            }
        }

        // unpack + horizontal add: v[r*8 + e]
        float v[RB * E];
        #pragma unroll
        for (int r = 0; r < RB; r++)
            #pragma unroll
            for (int e = 0; e < E; e++) {
                uint32_t lo, hi;
                asm("mov.b64 {%0, %1}, %2;" : "=r"(lo), "=r"(hi) : "l"(acc2[r][e]));
                v[r * E + e] = __uint_as_float(lo) + __uint_as_float(hi);
            }

        // Butterfly transpose-reduction: lane l ends with the full k-sum of
        // value index l (row l>>3, expert l&7).
        #pragma unroll
        for (int off = 16; off >= 1; off >>= 1) {
            const bool up = (lane & off) != 0;
            #pragma unroll
            for (int q = 0; q < off; q++) {
                float send = up ? v[q] : v[q + off];
                float recv = __shfl_xor_sync(0xffffffffu, send, off);
                v[q] = (up ? v[q + off] : v[q]) + recv;
            }
        }

        const int e   = lane & 7;
        const int row = row0 + (lane >> 3);
        const float logit = v[0] + b_sh[e];

        out_lg[(size_t)row * E + e] = logit;     // 32 consecutive floats/warp

        float lv[8];
        #pragma unroll
        for (int k = 0; k < 8; k++)
            lv[k] = __shfl_sync(0xffffffffu, logit, (lane & 24) | k);

        if (e == 0) {
            // top-1: strict >, lowest index wins ties (matches lax.top_k)
            int i1 = 0; float v1 = lv[0];
            #pragma unroll
            for (int k = 1; k < 8; k++)
                if (lv[k] > v1) { v1 = lv[k]; i1 = k; }
            int i2 = (i1 == 0) ? 1 : 0; float v2 = lv[i2];
            #pragma unroll
            for (int k = 0; k < 8; k++)
                if (k != i1 && lv[k] > v2) { v2 = lv[k]; i2 = k; }

            const float tt = __expf(v2 - v1);     // <= 1
            const float w1 = 1.0f / (1.0f + tt);
            const float w2 = tt * w1;

            out_idx[(size_t)row * 2]     = (float)i1;
            out_idx[(size_t)row * 2 + 1] = (float)i2;
            out_wt [(size_t)row * 2]     = w1;
            out_wt [(size_t)row * 2 + 1] = w2;
        }
    }
}

extern "C" void kernel_launch(void* const* d_in, const int* in_sizes, int n_in,
                              void* d_out, int out_size) {
    const float* h  = (const float*)d_in[0];   // [B, 768]
    const float* gw = (const float*)d_in[1];   // [8, 768]
    const float* gb = (const float*)d_in[2];   // [8]
    float* out = (float*)d_out;

    const int B = in_sizes[0] / D;             // 32768

    // smem: 24KB w + 192KB warp-private staging + bias + 16 mbarriers
    const int smem_bytes = (8 * DV + WRP * 2 * SLOT) * 16 + 64 + 16 * 8;
    cudaFuncSetAttribute(router_kernel,
                         cudaFuncAttributeMaxDynamicSharedMemorySize, smem_bytes);

    // persistent: 1 CTA per SM, warps self-paced over 8192 batches
    const int blocks = 148;
    router_kernel<<<blocks, THREADS, smem_bytes>>>(h, gw, gb, out, B);
}